// round 9
// baseline (speedup 1.0000x reference)
#include <cuda_runtime.h>
#include <cuda_bf16.h>
#include <math.h>
#include <stdint.h>

#define NN 8192
#define HH 128
#define RR 8
#define BB 64
#define LL 48
#define EE 65536
#define VAC 64
#define NSEG (NN * RR)

// ---------------- scratch (device globals; no allocation) ----------------
__device__ float g_x[NN * HH];
__device__ __nv_bfloat16 g_xhi[NN * HH];
__device__ __nv_bfloat16 g_xlo[NN * HH];
__device__ __nv_bfloat16 g_wthi[27 * HH * HH];
__device__ __nv_bfloat16 g_wtlo[27 * HH * HH];
__device__ float g_y[NN * HH];
__device__ float g_z[NN * RR * HH];
__device__ int g_cnt[NSEG];
__device__ int g_cur[NSEG];
__device__ int g_off[NSEG];
__device__ int g_bt[64];
__device__ int g_bt2[64];
__device__ int g_esrc[EE];
__device__ float g_hG[BB * HH];
__device__ float g_seqin[BB * LL * HH];
__device__ float g_xw[BB * LL * 3 * HH];
__device__ float g_seqout[BB * LL * HH];
__device__ float g_A[BB * LL * HH];
__device__ float g_C[NN * HH];

__device__ __forceinline__ uint32_t smem_u32(const void* p) {
    uint32_t a;
    asm("{ .reg .u64 t; cvta.to.shared.u64 t, %1; cvt.u32.u64 %0, t; }" : "=r"(a) : "l"(p));
    return a;
}

// ---------------- embed + bf16 split + CSR counter zero --------------------
__global__ void k_embed_split(const int* __restrict__ nt, const float* __restrict__ emb) {
    int i = blockIdx.x * blockDim.x + threadIdx.x;
    if (i < NSEG) { g_cnt[i] = 0; g_cur[i] = 0; }
    float v = emb[nt[i >> 7] * HH + (i & 127)];
    g_x[i] = v;
    __nv_bfloat16 hi = __float2bfloat16(v);
    g_xhi[i] = hi;
    g_xlo[i] = __float2bfloat16(v - __bfloat162float(hi));
}
__global__ void k_count(const int* __restrict__ ei, const int* __restrict__ ea) {
    int e = blockIdx.x * blockDim.x + threadIdx.x;
    if (e < EE) atomicAdd(&g_cnt[ei[EE + e] * RR + ea[e]], 1);
}

// ---------------- CSR build: 2-level scan + scatter ----------------
__global__ void __launch_bounds__(1024) k_scan1() {
    __shared__ int s[1024];
    int i = blockIdx.x * 1024 + threadIdx.x;
    int v = g_cnt[i];
    s[threadIdx.x] = v;
    __syncthreads();
#pragma unroll
    for (int off = 1; off < 1024; off <<= 1) {
        int t = (threadIdx.x >= off) ? s[threadIdx.x - off] : 0;
        __syncthreads();
        s[threadIdx.x] += t;
        __syncthreads();
    }
    g_off[i] = s[threadIdx.x] - v;
    if (threadIdx.x == 1023) g_bt[blockIdx.x] = s[1023];
}
__global__ void k_scan2() {
    __shared__ int s[64];
    int v = g_bt[threadIdx.x];
    s[threadIdx.x] = v;
    __syncthreads();
#pragma unroll
    for (int off = 1; off < 64; off <<= 1) {
        int t = (threadIdx.x >= off) ? s[threadIdx.x - off] : 0;
        __syncthreads();
        s[threadIdx.x] += t;
        __syncthreads();
    }
    g_bt2[threadIdx.x] = s[threadIdx.x] - v;
}
__global__ void k_scatter(const int* __restrict__ ei, const int* __restrict__ ea) {
    int e = blockIdx.x * blockDim.x + threadIdx.x;
    if (e >= EE) return;
    int seg = ei[EE + e] * RR + ea[e];
    int pos = g_off[seg] + g_bt2[seg >> 10] + atomicAdd(&g_cur[seg], 1);
    g_esrc[pos] = ei[e];
}

// ---------------- weight transpose + split (smem-tiled) --------------------
__global__ void k_convw(const float* __restrict__ rel, const float* __restrict__ root) {
    __shared__ float ts[32][33];
    int w = blockIdx.y;
    int li = w / 9, cb = w % 9;
    const float* W = (cb < 8) ? rel + (size_t)(li * 8 + cb) * (HH * HH)
                              : root + (size_t)li * (HH * HH);
    int tx = (blockIdx.x & 3) * 32;
    int ty = (blockIdx.x >> 2) * 32;
    int r = threadIdx.x >> 5;
    int c = threadIdx.x & 31;
#pragma unroll
    for (int i = 0; i < 32; i += 8)
        ts[r + i][c] = W[(size_t)(ty + r + i) * HH + tx + c];
    __syncthreads();
    size_t base = (size_t)w * HH * HH;
#pragma unroll
    for (int i = 0; i < 32; i += 8) {
        float v = ts[c][r + i];
        __nv_bfloat16 hi = __float2bfloat16(v);
        size_t p = base + (size_t)(tx + r + i) * HH + ty + c;
        g_wthi[p] = hi;
        g_wtlo[p] = __float2bfloat16(v - __bfloat162float(hi));
    }
}

// ======= RGCN GEMM: mma.sync bf16, 64-row M tiles, 2 CTAs/SM ===============
#define LDT 136
#define TILE_A (64 * LDT * 2)       // 17408 B
#define TILE_BB (128 * LDT * 2)     // 34816 B
#define RGCN_SMEM (2 * TILE_A + 2 * TILE_BB)   // 104448 B

#define MMA16816(d, a0, a1, a2, a3, b0, b1)                                 \
    asm volatile("mma.sync.aligned.m16n8k16.row.col.f32.bf16.bf16.f32 "     \
                 "{%0,%1,%2,%3}, {%4,%5,%6,%7}, {%8,%9}, {%0,%1,%2,%3};"    \
                 : "+f"((d)[0]), "+f"((d)[1]), "+f"((d)[2]), "+f"((d)[3])   \
                 : "r"(a0), "r"(a1), "r"(a2), "r"(a3), "r"(b0), "r"(b1))

#define LDMX4(r0, r1, r2, r3, addr)                                         \
    asm volatile("ldmatrix.sync.aligned.m8n8.x4.shared.b16 {%0,%1,%2,%3}, [%4];" \
                 : "=r"(r0), "=r"(r1), "=r"(r2), "=r"(r3) : "r"(addr))

__global__ void __launch_bounds__(256, 2) k_rgcn_mma(const float* __restrict__ bias, int li) {
    extern __shared__ char sm[];
    __shared__ float s_bias[HH];

    int tid = threadIdx.x;
    int cb = blockIdx.x, mb = blockIdx.y;
    int m0 = mb * 64;
    int widx = li * 9 + cb;

    if (cb == 8 && tid < HH) s_bias[tid] = bias[li * HH + tid];

    {
        // A tiles: 64 rows (1024 uint4); B tiles: 128 rows (2048 uint4)
        const uint4* srcs[4] = {
            (const uint4*)(g_xhi + (size_t)m0 * HH),
            (const uint4*)(g_xlo + (size_t)m0 * HH),
            (const uint4*)(g_wthi + (size_t)widx * HH * HH),
            (const uint4*)(g_wtlo + (size_t)widx * HH * HH)};
        const int offb[4] = {0, TILE_A, 2 * TILE_A, 2 * TILE_A + TILE_BB};
        const int nchk[4] = {1024, 1024, 2048, 2048};
#pragma unroll
        for (int ti = 0; ti < 4; ti++) {
            const uint4* src = srcs[ti];
            char* dst = sm + offb[ti];
            for (int c = tid; c < nchk[ti]; c += 256) {
                int r = c >> 4, q = c & 15;
                *(uint4*)(dst + r * (LDT * 2) + q * 16) = src[r * 16 + q];
            }
        }
    }
    __syncthreads();

    int lane = tid & 31, wid = tid >> 5;
    int warpM = wid & 1;       // 0..1 -> 32-row slab
    int warpN = wid >> 1;      // 0..3 -> 32-col slab
    int g = lane >> 2, tg = lane & 3;

    uint32_t smbase = smem_u32(sm);
    uint32_t aOff = (uint32_t)((warpM * 32 + (lane & 15)) * LDT + ((lane & 16) ? 8 : 0)) * 2;
    uint32_t bOff = (uint32_t)((warpN * 32 + (lane & 7) + ((lane & 16) ? 8 : 0)) * LDT +
                               ((lane & 8) ? 8 : 0)) * 2;

    uint32_t aH = smbase + aOff;
    uint32_t aL = smbase + TILE_A + aOff;
    uint32_t bH = smbase + 2 * TILE_A + bOff;
    uint32_t bL = smbase + 2 * TILE_A + TILE_BB + bOff;

    float acc[2][4][4];
#pragma unroll
    for (int mi = 0; mi < 2; mi++)
#pragma unroll
        for (int nf = 0; nf < 4; nf++)
#pragma unroll
            for (int j = 0; j < 4; j++) acc[mi][nf][j] = 0.f;

#pragma unroll
    for (int kc = 0; kc < 8; kc++) {
        uint32_t kb = kc * 32;
        uint32_t ah[2][4], al[2][4];
        LDMX4(ah[0][0], ah[0][1], ah[0][2], ah[0][3], aH + kb);
        LDMX4(ah[1][0], ah[1][1], ah[1][2], ah[1][3], aH + 16 * LDT * 2 + kb);
        LDMX4(al[0][0], al[0][1], al[0][2], al[0][3], aL + kb);
        LDMX4(al[1][0], al[1][1], al[1][2], al[1][3], aL + 16 * LDT * 2 + kb);
#pragma unroll
        for (int p = 0; p < 2; p++) {
            uint32_t bh0, bh1, bh2, bh3, bl0, bl1, bl2, bl3;
            LDMX4(bh0, bh1, bh2, bh3, bH + p * (16 * LDT * 2) + kb);
            LDMX4(bl0, bl1, bl2, bl3, bL + p * (16 * LDT * 2) + kb);
#pragma unroll
            for (int mi = 0; mi < 2; mi++) {
                MMA16816(acc[mi][2 * p],     ah[mi][0], ah[mi][1], ah[mi][2], ah[mi][3], bh0, bh1);
                MMA16816(acc[mi][2 * p + 1], ah[mi][0], ah[mi][1], ah[mi][2], ah[mi][3], bh2, bh3);
                MMA16816(acc[mi][2 * p],     ah[mi][0], ah[mi][1], ah[mi][2], ah[mi][3], bl0, bl1);
                MMA16816(acc[mi][2 * p + 1], ah[mi][0], ah[mi][1], ah[mi][2], ah[mi][3], bl2, bl3);
                MMA16816(acc[mi][2 * p],     al[mi][0], al[mi][1], al[mi][2], al[mi][3], bh0, bh1);
                MMA16816(acc[mi][2 * p + 1], al[mi][0], al[mi][1], al[mi][2], al[mi][3], bh2, bh3);
            }
        }
    }

#pragma unroll
    for (int mi = 0; mi < 2; mi++) {
        int r0 = m0 + warpM * 32 + mi * 16 + g;
#pragma unroll
        for (int nf = 0; nf < 4; nf++) {
            int col = warpN * 32 + nf * 8 + tg * 2;
            if (cb < 8) {
                float2* z0 = (float2*)(g_z + (size_t)r0 * (RR * HH) + cb * HH + col);
                float2* z1 = (float2*)(g_z + (size_t)(r0 + 8) * (RR * HH) + cb * HH + col);
                *z0 = make_float2(acc[mi][nf][0], acc[mi][nf][1]);
                *z1 = make_float2(acc[mi][nf][2], acc[mi][nf][3]);
            } else {
                float b0 = s_bias[col], b1 = s_bias[col + 1];
                float2* y0 = (float2*)(g_y + (size_t)r0 * HH + col);
                float2* y1 = (float2*)(g_y + (size_t)(r0 + 8) * HH + col);
                *y0 = make_float2(acc[mi][nf][0] + b0, acc[mi][nf][1] + b1);
                *y1 = make_float2(acc[mi][nf][2] + b0, acc[mi][nf][3] + b1);
            }
        }
    }
}

// ------------- gather + relu + bf16 split: warp per dst node (R7) ----------
__device__ __forceinline__ int segoff(int s) { return g_off[s] + g_bt2[s >> 10]; }

__global__ void __launch_bounds__(256) k_gather_relu() {
    int node = (blockIdx.x * blockDim.x + threadIdx.x) >> 5;
    int lane = threadIdx.x & 31;
    if (node >= NN) return;

    float4 acc = ((const float4*)(g_y + (size_t)node * HH))[lane];
    int st = segoff(node * RR);
#pragma unroll
    for (int r = 0; r < RR; r++) {
        int sn = node * RR + r + 1;
        int en = (sn < NSEG) ? segoff(sn) : EE;
        int cnt = en - st;
        if (cnt > 0) {
            float4 a = make_float4(0.f, 0.f, 0.f, 0.f);
            for (int j = st; j < en; j++) {
                int src = g_esrc[j];
                float4 z = *(const float4*)&g_z[(size_t)src * (RR * HH) + r * HH + lane * 4];
                a.x += z.x; a.y += z.y; a.z += z.z; a.w += z.w;
            }
            float sc = 1.0f / (float)cnt;
            acc.x += a.x * sc; acc.y += a.y * sc;
            acc.z += a.z * sc; acc.w += a.w * sc;
        }
        st = en;
    }
    acc.x = fmaxf(acc.x, 0.f); acc.y = fmaxf(acc.y, 0.f);
    acc.z = fmaxf(acc.z, 0.f); acc.w = fmaxf(acc.w, 0.f);

    ((float4*)(g_x + (size_t)node * HH))[lane] = acc;

    __nv_bfloat162 h0 = make_bfloat162(__float2bfloat16(acc.x), __float2bfloat16(acc.y));
    __nv_bfloat162 h1 = make_bfloat162(__float2bfloat16(acc.z), __float2bfloat16(acc.w));
    __nv_bfloat162 l0 = make_bfloat162(
        __float2bfloat16(acc.x - __bfloat162float(h0.x)),
        __float2bfloat16(acc.y - __bfloat162float(h0.y)));
    __nv_bfloat162 l1 = make_bfloat162(
        __float2bfloat16(acc.z - __bfloat162float(h1.x)),
        __float2bfloat16(acc.w - __bfloat162float(h1.y)));
    ((__nv_bfloat162*)(g_xhi + (size_t)node * HH))[lane * 2] = h0;
    ((__nv_bfloat162*)(g_xhi + (size_t)node * HH))[lane * 2 + 1] = h1;
    ((__nv_bfloat162*)(g_xlo + (size_t)node * HH))[lane * 2] = l0;
    ((__nv_bfloat162*)(g_xlo + (size_t)node * HH))[lane * 2 + 1] = l1;
}

// ---------------- pool + action head + sos (fused, block per graph) --------
__global__ void k_pool_action_sos(const int* __restrict__ nodes_bs,
                                  const float* __restrict__ wA, const float* __restrict__ bA,
                                  const float* __restrict__ wAf, const float* __restrict__ bAf,
                                  const int* __restrict__ act, const float* __restrict__ embA,
                                  float* __restrict__ out) {
    int b = blockIdx.x, o = threadIdx.x;
    __shared__ float sg[HH], t1[HH];
    float s = 0.f;
    const float* xp = g_x + (size_t)b * (NN / BB) * HH + o;
#pragma unroll 4
    for (int j = 0; j < NN / BB; j++) s += xp[j * HH];
    s /= (float)nodes_bs[b];
    g_hG[b * HH + o] = s;
    sg[o] = s;
    g_seqin[(size_t)b * LL * HH + o] = embA[act[b] * HH + o];
    __syncthreads();
    float acc = bA[o];
    const float* w = wA + o * HH;
#pragma unroll 8
    for (int h = 0; h < HH; h += 4) {
        float4 w4 = *(const float4*)&w[h];
        acc += sg[h] * w4.x + sg[h + 1] * w4.y + sg[h + 2] * w4.z + sg[h + 3] * w4.w;
    }
    t1[o] = fmaxf(acc, 0.f);
    __syncthreads();
    if (o < VAC) {
        float a2 = bAf[o];
        const float* w2 = wAf + o * HH;
#pragma unroll 8
        for (int h = 0; h < HH; h += 4) {
            float4 w4 = *(const float4*)&w2[h];
            a2 += t1[h] * w4.x + t1[h + 1] * w4.y + t1[h + 2] * w4.z + t1[h + 3] * w4.w;
        }
        out[b * VAC + o] = a2;
    }
}

// ---------------- GRU input assembly ----------------
__global__ void k_seqemb(const float* __restrict__ seq) {
    int t = blockIdx.x;
    int b = blockIdx.y;
    int h = threadIdx.x;
    __shared__ float s[NN / BB];
    s[h] = seq[(size_t)(b * (NN / BB) + h) * LL + t];
    __syncthreads();
    float acc = 0.f;
    for (int j = 0; j < NN / BB; j++) {
        float sv = s[j];
        if (sv != 0.0f)
            acc += sv * g_x[(size_t)(b * (NN / BB) + j) * HH + h];
    }
    g_seqin[((size_t)b * LL + t + 1) * HH + h] = acc;
}

// ---------------- generic C[m,j] = dot(X[m,:], W[j, woff:woff+128]) + bias -
__global__ void k_gemmT(const float* __restrict__ X, const float* __restrict__ W,
                        int ldw, int woff, const float* __restrict__ bias,
                        float* __restrict__ out) {
    int m0 = blockIdx.x * 16;
    int j = threadIdx.x;
    int J = blockDim.x;
    __shared__ float Xs[16 * HH];
    for (int idx = j; idx < 16 * HH; idx += J) Xs[idx] = X[(size_t)m0 * HH + idx];
    __syncthreads();
    float acc[16];
    float bv = bias ? bias[j] : 0.f;
#pragma unroll
    for (int m = 0; m < 16; m++) acc[m] = bv;
    const float* wr = W + (size_t)j * ldw + woff;
    for (int h = 0; h < HH; h += 4) {
        float4 w4 = *(const float4*)&wr[h];
#pragma unroll
        for (int m = 0; m < 16; m++) {
            acc[m] += Xs[m * HH + h] * w4.x;
            acc[m] += Xs[m * HH + h + 1] * w4.y;
            acc[m] += Xs[m * HH + h + 2] * w4.z;
            acc[m] += Xs[m * HH + h + 3] * w4.w;
        }
    }
#pragma unroll
    for (int m = 0; m < 16; m++) out[(size_t)(m0 + m) * J + j] = acc[m];
}

// node-head A and C in one grid
__global__ void k_gemmT_AC(const float* __restrict__ W, const float* __restrict__ biasN) {
    int bx = blockIdx.x;
    const float* X;
    const float* bias;
    int woff;
    float* out;
    int m0;
    if (bx < (BB * LL) / 16) {
        X = g_seqout; woff = 0; bias = nullptr; out = g_A; m0 = bx * 16;
    } else {
        X = g_x; woff = HH; bias = biasN; out = g_C; m0 = (bx - (BB * LL) / 16) * 16;
    }
    int j = threadIdx.x;
    __shared__ float Xs[16 * HH];
    for (int idx = j; idx < 16 * HH; idx += HH) Xs[idx] = X[(size_t)m0 * HH + idx];
    __syncthreads();
    float acc[16];
    float bv = bias ? bias[j] : 0.f;
#pragma unroll
    for (int m = 0; m < 16; m++) acc[m] = bv;
    const float* wr = W + (size_t)j * (2 * HH) + woff;
    for (int h = 0; h < HH; h += 4) {
        float4 w4 = *(const float4*)&wr[h];
#pragma unroll
        for (int m = 0; m < 16; m++) {
            acc[m] += Xs[m * HH + h] * w4.x;
            acc[m] += Xs[m * HH + h + 1] * w4.y;
            acc[m] += Xs[m * HH + h + 2] * w4.z;
            acc[m] += Xs[m * HH + h + 3] * w4.w;
        }
    }
#pragma unroll
    for (int m = 0; m < 16; m++) out[(size_t)(m0 + m) * HH + j] = acc[m];
}

// ---------------- GRU scan (float4 smem reads, R7 version) ----------------
__global__ void __launch_bounds__(384) k_gru(const float* __restrict__ w_hh,
                                             const float* __restrict__ b_hh,
                                             const int* __restrict__ len_seq) {
    int b = blockIdx.x;
    int g = threadIdx.x;
    __shared__ __align__(16) float sh[HH];
    __shared__ float sg[3 * HH];
    if (g < HH) sh[g] = g_hG[b * HH + g];
    int ls = len_seq[b];
    const float* w = w_hh + (size_t)g * HH;
    float bg = b_hh[g];
    __syncthreads();
    const float4* sh4 = (const float4*)sh;
    for (int t = 0; t < LL; t++) {
        float acc = bg;
#pragma unroll
        for (int k = 0; k < HH / 4; k++) {
            float4 w4 = *(const float4*)&w[k * 4];
            float4 h4 = sh4[k];
            acc += h4.x * w4.x + h4.y * w4.y + h4.z * w4.z + h4.w * w4.w;
        }
        sg[g] = acc;
        __syncthreads();
        if (g < HH) {
            const float* xwp = g_xw + ((size_t)b * LL + t) * (3 * HH);
            float rg = 1.f / (1.f + expf(-(xwp[g] + sg[g])));
            float zg = 1.f / (1.f + expf(-(xwp[HH + g] + sg[HH + g])));
            float ng = tanhf(xwp[2 * HH + g] + rg * sg[2 * HH + g]);
            float hnew = (1.f - zg) * ng + zg * sh[g];
            g_seqout[((size_t)b * LL + t) * HH + g] = (t < ls) ? hnew : 0.f;
            sh[g] = hnew;
        }
        __syncthreads();
    }
}

// ---------------- node logits ----------------
__global__ void k_logits(const int* __restrict__ bs, const float* __restrict__ wf,
                         const float* __restrict__ bf, float* __restrict__ outN) {
    int i = (blockIdx.x * blockDim.x + threadIdx.x) >> 5;
    int lane = threadIdx.x & 31;
    if (i >= NN) return;
    int b = bs[i];
    float4 c4 = *(const float4*)&g_C[(size_t)i * HH + lane * 4];
    float4 w4 = *(const float4*)&wf[lane * 4];
    float bias = bf[0];
    const float* Ab = g_A + (size_t)b * LL * HH;
    for (int t = 0; t < LL; t++) {
        float4 a4 = *(const float4*)&Ab[t * HH + lane * 4];
        float s = fmaxf(a4.x + c4.x, 0.f) * w4.x
                + fmaxf(a4.y + c4.y, 0.f) * w4.y
                + fmaxf(a4.z + c4.z, 0.f) * w4.z
                + fmaxf(a4.w + c4.w, 0.f) * w4.w;
#pragma unroll
        for (int off = 16; off; off >>= 1) s += __shfl_down_sync(0xffffffffu, s, off);
        if (lane == 0) outN[(size_t)i * LL + t] = s + bias;
    }
}

// ---------------- per-graph softmax, coalesced -----------------------------
#define NPG (NN / BB)
__global__ void __launch_bounds__(256) k_softmax2(float* __restrict__ outN) {
    int b = blockIdx.x;
    __shared__ float sm[LL * 129];
    __shared__ float smax[LL], ssum[LL];
    int tid = threadIdx.x;
    float* base = outN + (size_t)b * NPG * LL;

    for (int idx = tid; idx < NPG * LL; idx += 256) {
        int node = idx / LL, t = idx % LL;
        sm[t * 129 + node] = base[idx];
    }
    __syncthreads();

    int w = tid >> 5, lane = tid & 31;
    for (int t = w; t < LL; t += 8) {
        float v0 = sm[t * 129 + lane];
        float v1 = sm[t * 129 + lane + 32];
        float v2 = sm[t * 129 + lane + 64];
        float v3 = sm[t * 129 + lane + 96];
        float mx = fmaxf(fmaxf(v0, v1), fmaxf(v2, v3));
#pragma unroll
        for (int off = 16; off; off >>= 1)
            mx = fmaxf(mx, __shfl_xor_sync(0xffffffffu, mx, off));
        float e = expf(v0 - mx) + expf(v1 - mx) + expf(v2 - mx) + expf(v3 - mx);
#pragma unroll
        for (int off = 16; off; off >>= 1) e += __shfl_xor_sync(0xffffffffu, e, off);
        if (lane == 0) { smax[t] = mx; ssum[t] = e; }
    }
    __syncthreads();

    for (int idx = tid; idx < NPG * LL; idx += 256) {
        int node = idx / LL, t = idx % LL;
        base[idx] = expf(sm[t * 129 + node] - smax[t]) / ssum[t];
    }
}

// ---------------- launch ----------------
extern "C" void kernel_launch(void* const* d_in, const int* in_sizes, int n_in,
                              void* d_out, int out_size) {
    const int* nodeTypes   = (const int*)d_in[0];
    const int* edge_index  = (const int*)d_in[1];
    const int* edge_attr   = (const int*)d_in[2];
    const int* bs          = (const int*)d_in[3];
    const int* nodes_bs    = (const int*)d_in[4];
    const int* len_seq     = (const int*)d_in[5];
    const float* seq       = (const float*)d_in[6];
    const int* action_in   = (const int*)d_in[7];
    const float* emb_nodes = (const float*)d_in[8];
    const float* emb_act   = (const float*)d_in[9];
    const float* rgcn_rel  = (const float*)d_in[10];
    const float* rgcn_root = (const float*)d_in[11];
    const float* rgcn_bias = (const float*)d_in[12];
    const float* gru_w_ih  = (const float*)d_in[13];
    const float* gru_w_hh  = (const float*)d_in[14];
    const float* gru_b_ih  = (const float*)d_in[15];
    const float* gru_b_hh  = (const float*)d_in[16];
    const float* linA_w    = (const float*)d_in[17];
    const float* linA_b    = (const float*)d_in[18];
    const float* linAf_w   = (const float*)d_in[19];
    const float* linAf_b   = (const float*)d_in[20];
    const float* linN_w    = (const float*)d_in[21];
    const float* linN_b    = (const float*)d_in[22];
    const float* linNf_w   = (const float*)d_in[23];
    const float* linNf_b   = (const float*)d_in[24];

    float* out_action = (float*)d_out;
    float* out_nodes  = out_action + BB * VAC;

    float *p_seqin, *p_xw;
    cudaGetSymbolAddress((void**)&p_seqin, g_seqin);
    cudaGetSymbolAddress((void**)&p_xw, g_xw);

    cudaFuncSetAttribute(k_rgcn_mma, cudaFuncAttributeMaxDynamicSharedMemorySize, RGCN_SMEM);

    k_embed_split<<<(NN * HH) / 256, 256>>>(nodeTypes, emb_nodes);
    k_count<<<EE / 256, 256>>>(edge_index, edge_attr);
    k_convw<<<dim3(16, 27), 256>>>(rgcn_rel, rgcn_root);

    // 4: profiled slot — the tensor-core GEMM
    k_rgcn_mma<<<dim3(9, 128), 256, RGCN_SMEM>>>(rgcn_bias, 0);

    k_scan1<<<64, 1024>>>();
    k_scan2<<<1, 64>>>();
    k_scatter<<<EE / 256, 256>>>(edge_index, edge_attr);

    k_gather_relu<<<NN / 8, 256>>>();
    for (int li = 1; li < 3; li++) {
        k_rgcn_mma<<<dim3(9, 128), 256, RGCN_SMEM>>>(rgcn_bias, li);
        k_gather_relu<<<NN / 8, 256>>>();
    }

    k_pool_action_sos<<<BB, HH>>>(nodes_bs, linA_w, linA_b, linAf_w, linAf_b,
                                  action_in, emb_act, out_action);
    k_seqemb<<<dim3(LL - 1, BB), NN / BB>>>(seq);

    k_gemmT<<<(BB * LL) / 16, 3 * HH>>>(p_seqin, gru_w_ih, HH, 0, gru_b_ih, p_xw);
    k_gru<<<BB, 3 * HH>>>(gru_w_hh, gru_b_hh, len_seq);

    k_gemmT_AC<<<(BB * LL) / 16 + NN / 16, HH>>>(linN_w, linN_b);
    k_logits<<<NN / 8, 256>>>(bs, linNf_w, linNf_b, out_nodes);
    k_softmax2<<<BB, 256>>>(out_nodes);
}

// round 10
// speedup vs baseline: 1.6704x; 1.6704x over previous
#include <cuda_runtime.h>
#include <cuda_bf16.h>
#include <math.h>
#include <stdint.h>

#define NN 8192
#define HH 128
#define RR 8
#define BB 64
#define LL 48
#define EE 65536
#define VAC 64
#define NSEG (NN * RR)

// ---------------- scratch (device globals; no allocation) ----------------
__device__ float g_x[NN * HH];
__device__ __nv_bfloat16 g_xhi[NN * HH];
__device__ __nv_bfloat16 g_xlo[NN * HH];
__device__ __nv_bfloat16 g_wthi[27 * HH * HH];
__device__ __nv_bfloat16 g_wtlo[27 * HH * HH];
__device__ float g_y[NN * HH];
__device__ float g_z[NN * RR * HH];
__device__ int g_cnt[NSEG];
__device__ int g_cur[NSEG];
__device__ int g_off[NSEG];
__device__ int g_bt[64];
__device__ int g_bt2[64];
__device__ int g_esrc[EE];
__device__ float g_hG[BB * HH];
__device__ float g_seqin[BB * LL * HH];
__device__ float g_xw[BB * LL * 3 * HH];
__device__ float g_seqout[BB * LL * HH];
__device__ float g_A[BB * LL * HH];
__device__ float g_C[NN * HH];

__device__ __forceinline__ uint32_t smem_u32(const void* p) {
    uint32_t a;
    asm("{ .reg .u64 t; cvta.to.shared.u64 t, %1; cvt.u32.u64 %0, t; }" : "=r"(a) : "l"(p));
    return a;
}

// ---------------- embed + bf16 split + CSR counter zero --------------------
__global__ void k_embed_split(const int* __restrict__ nt, const float* __restrict__ emb) {
    int i = blockIdx.x * blockDim.x + threadIdx.x;
    if (i < NSEG) { g_cnt[i] = 0; g_cur[i] = 0; }
    float v = emb[nt[i >> 7] * HH + (i & 127)];
    g_x[i] = v;
    __nv_bfloat16 hi = __float2bfloat16(v);
    g_xhi[i] = hi;
    g_xlo[i] = __float2bfloat16(v - __bfloat162float(hi));
}
__global__ void k_count(const int* __restrict__ ei, const int* __restrict__ ea) {
    int e = blockIdx.x * blockDim.x + threadIdx.x;
    if (e < EE) atomicAdd(&g_cnt[ei[EE + e] * RR + ea[e]], 1);
}

// ---------------- CSR build: 2-level scan + scatter ----------------
__global__ void __launch_bounds__(1024) k_scan1() {
    __shared__ int s[1024];
    int i = blockIdx.x * 1024 + threadIdx.x;
    int v = g_cnt[i];
    s[threadIdx.x] = v;
    __syncthreads();
#pragma unroll
    for (int off = 1; off < 1024; off <<= 1) {
        int t = (threadIdx.x >= off) ? s[threadIdx.x - off] : 0;
        __syncthreads();
        s[threadIdx.x] += t;
        __syncthreads();
    }
    g_off[i] = s[threadIdx.x] - v;
    if (threadIdx.x == 1023) g_bt[blockIdx.x] = s[1023];
}
__global__ void k_scan2() {
    __shared__ int s[64];
    int v = g_bt[threadIdx.x];
    s[threadIdx.x] = v;
    __syncthreads();
#pragma unroll
    for (int off = 1; off < 64; off <<= 1) {
        int t = (threadIdx.x >= off) ? s[threadIdx.x - off] : 0;
        __syncthreads();
        s[threadIdx.x] += t;
        __syncthreads();
    }
    g_bt2[threadIdx.x] = s[threadIdx.x] - v;
}
__global__ void k_scatter(const int* __restrict__ ei, const int* __restrict__ ea) {
    int e = blockIdx.x * blockDim.x + threadIdx.x;
    if (e >= EE) return;
    int seg = ei[EE + e] * RR + ea[e];
    int pos = g_off[seg] + g_bt2[seg >> 10] + atomicAdd(&g_cur[seg], 1);
    g_esrc[pos] = ei[e];
}

// ---------------- weight transpose + split (smem-tiled) --------------------
__global__ void k_convw(const float* __restrict__ rel, const float* __restrict__ root) {
    __shared__ float ts[32][33];
    int w = blockIdx.y;
    int li = w / 9, cb = w % 9;
    const float* W = (cb < 8) ? rel + (size_t)(li * 8 + cb) * (HH * HH)
                              : root + (size_t)li * (HH * HH);
    int tx = (blockIdx.x & 3) * 32;
    int ty = (blockIdx.x >> 2) * 32;
    int r = threadIdx.x >> 5;
    int c = threadIdx.x & 31;
#pragma unroll
    for (int i = 0; i < 32; i += 8)
        ts[r + i][c] = W[(size_t)(ty + r + i) * HH + tx + c];
    __syncthreads();
    size_t base = (size_t)w * HH * HH;
#pragma unroll
    for (int i = 0; i < 32; i += 8) {
        float v = ts[c][r + i];
        __nv_bfloat16 hi = __float2bfloat16(v);
        size_t p = base + (size_t)(tx + r + i) * HH + ty + c;
        g_wthi[p] = hi;
        g_wtlo[p] = __float2bfloat16(v - __bfloat162float(hi));
    }
}

// ====== RGCN GEMM: mma.sync bf16, 128-row tiles, 512 thr, 4Mx4N (R8) =======
#define LDT 136
#define TILE_B (128 * LDT * 2)
#define RGCN_SMEM (4 * TILE_B)

#define MMA16816(d, a0, a1, a2, a3, b0, b1)                                 \
    asm volatile("mma.sync.aligned.m16n8k16.row.col.f32.bf16.bf16.f32 "     \
                 "{%0,%1,%2,%3}, {%4,%5,%6,%7}, {%8,%9}, {%0,%1,%2,%3};"    \
                 : "+f"((d)[0]), "+f"((d)[1]), "+f"((d)[2]), "+f"((d)[3])   \
                 : "r"(a0), "r"(a1), "r"(a2), "r"(a3), "r"(b0), "r"(b1))

#define LDMX4(r0, r1, r2, r3, addr)                                         \
    asm volatile("ldmatrix.sync.aligned.m8n8.x4.shared.b16 {%0,%1,%2,%3}, [%4];" \
                 : "=r"(r0), "=r"(r1), "=r"(r2), "=r"(r3) : "r"(addr))

__global__ void __launch_bounds__(512) k_rgcn_mma(const float* __restrict__ bias, int li) {
    extern __shared__ char sm[];
    __shared__ float s_bias[HH];

    int tid = threadIdx.x;
    int cb = blockIdx.x, mb = blockIdx.y;
    int m0 = mb * 128;
    int widx = li * 9 + cb;

    if (cb == 8 && tid < HH) s_bias[tid] = bias[li * HH + tid];

    {
        const uint4* srcs[4] = {
            (const uint4*)(g_xhi + (size_t)m0 * HH),
            (const uint4*)(g_xlo + (size_t)m0 * HH),
            (const uint4*)(g_wthi + (size_t)widx * HH * HH),
            (const uint4*)(g_wtlo + (size_t)widx * HH * HH)};
#pragma unroll
        for (int ti = 0; ti < 4; ti++) {
            const uint4* src = srcs[ti];
            char* dst = sm + ti * TILE_B;
#pragma unroll
            for (int t = 0; t < 4; t++) {
                int c = tid + t * 512;
                int r = c >> 4, q = c & 15;
                *(uint4*)(dst + r * (LDT * 2) + q * 16) = src[r * 16 + q];
            }
        }
    }
    __syncthreads();

    int lane = tid & 31, wid = tid >> 5;
    int warpM = wid & 3;       // 0..3 -> 32-row slab
    int warpN = wid >> 2;      // 0..3 -> 32-col slab
    int g = lane >> 2, tg = lane & 3;

    uint32_t smbase = smem_u32(sm);
    uint32_t aOff = (uint32_t)((warpM * 32 + (lane & 15)) * LDT + ((lane & 16) ? 8 : 0)) * 2;
    uint32_t bOff = (uint32_t)((warpN * 32 + (lane & 7) + ((lane & 16) ? 8 : 0)) * LDT +
                               ((lane & 8) ? 8 : 0)) * 2;

    uint32_t aH = smbase + aOff;
    uint32_t aL = smbase + TILE_B + aOff;
    uint32_t bH = smbase + 2 * TILE_B + bOff;
    uint32_t bL = smbase + 3 * TILE_B + bOff;

    float acc[2][4][4];
#pragma unroll
    for (int mi = 0; mi < 2; mi++)
#pragma unroll
        for (int nf = 0; nf < 4; nf++)
#pragma unroll
            for (int j = 0; j < 4; j++) acc[mi][nf][j] = 0.f;

#pragma unroll
    for (int kc = 0; kc < 8; kc++) {
        uint32_t kb = kc * 32;
        uint32_t ah[2][4], al[2][4];
        LDMX4(ah[0][0], ah[0][1], ah[0][2], ah[0][3], aH + kb);
        LDMX4(ah[1][0], ah[1][1], ah[1][2], ah[1][3], aH + 16 * LDT * 2 + kb);
        LDMX4(al[0][0], al[0][1], al[0][2], al[0][3], aL + kb);
        LDMX4(al[1][0], al[1][1], al[1][2], al[1][3], aL + 16 * LDT * 2 + kb);
#pragma unroll
        for (int p = 0; p < 2; p++) {
            uint32_t bh0, bh1, bh2, bh3, bl0, bl1, bl2, bl3;
            LDMX4(bh0, bh1, bh2, bh3, bH + p * (16 * LDT * 2) + kb);
            LDMX4(bl0, bl1, bl2, bl3, bL + p * (16 * LDT * 2) + kb);
#pragma unroll
            for (int mi = 0; mi < 2; mi++) {
                MMA16816(acc[mi][2 * p],     ah[mi][0], ah[mi][1], ah[mi][2], ah[mi][3], bh0, bh1);
                MMA16816(acc[mi][2 * p + 1], ah[mi][0], ah[mi][1], ah[mi][2], ah[mi][3], bh2, bh3);
                MMA16816(acc[mi][2 * p],     ah[mi][0], ah[mi][1], ah[mi][2], ah[mi][3], bl0, bl1);
                MMA16816(acc[mi][2 * p + 1], ah[mi][0], ah[mi][1], ah[mi][2], ah[mi][3], bl2, bl3);
                MMA16816(acc[mi][2 * p],     al[mi][0], al[mi][1], al[mi][2], al[mi][3], bh0, bh1);
                MMA16816(acc[mi][2 * p + 1], al[mi][0], al[mi][1], al[mi][2], al[mi][3], bh2, bh3);
            }
        }
    }

#pragma unroll
    for (int mi = 0; mi < 2; mi++) {
        int r0 = m0 + warpM * 32 + mi * 16 + g;
#pragma unroll
        for (int nf = 0; nf < 4; nf++) {
            int col = warpN * 32 + nf * 8 + tg * 2;
            if (cb < 8) {
                float2* z0 = (float2*)(g_z + (size_t)r0 * (RR * HH) + cb * HH + col);
                float2* z1 = (float2*)(g_z + (size_t)(r0 + 8) * (RR * HH) + cb * HH + col);
                *z0 = make_float2(acc[mi][nf][0], acc[mi][nf][1]);
                *z1 = make_float2(acc[mi][nf][2], acc[mi][nf][3]);
            } else {
                float b0 = s_bias[col], b1 = s_bias[col + 1];
                float2* y0 = (float2*)(g_y + (size_t)r0 * HH + col);
                float2* y1 = (float2*)(g_y + (size_t)(r0 + 8) * HH + col);
                *y0 = make_float2(acc[mi][nf][0] + b0, acc[mi][nf][1] + b1);
                *y1 = make_float2(acc[mi][nf][2] + b0, acc[mi][nf][3] + b1);
            }
        }
    }
}

// ------------- gather + relu + bf16 split: warp per dst node (R7) ----------
__device__ __forceinline__ int segoff(int s) { return g_off[s] + g_bt2[s >> 10]; }

__global__ void __launch_bounds__(256) k_gather_relu() {
    int node = (blockIdx.x * blockDim.x + threadIdx.x) >> 5;
    int lane = threadIdx.x & 31;
    if (node >= NN) return;

    float4 acc = ((const float4*)(g_y + (size_t)node * HH))[lane];
    int st = segoff(node * RR);
#pragma unroll
    for (int r = 0; r < RR; r++) {
        int sn = node * RR + r + 1;
        int en = (sn < NSEG) ? segoff(sn) : EE;
        int cnt = en - st;
        if (cnt > 0) {
            float4 a = make_float4(0.f, 0.f, 0.f, 0.f);
            for (int j = st; j < en; j++) {
                int src = g_esrc[j];
                float4 z = *(const float4*)&g_z[(size_t)src * (RR * HH) + r * HH + lane * 4];
                a.x += z.x; a.y += z.y; a.z += z.z; a.w += z.w;
            }
            float sc = 1.0f / (float)cnt;
            acc.x += a.x * sc; acc.y += a.y * sc;
            acc.z += a.z * sc; acc.w += a.w * sc;
        }
        st = en;
    }
    acc.x = fmaxf(acc.x, 0.f); acc.y = fmaxf(acc.y, 0.f);
    acc.z = fmaxf(acc.z, 0.f); acc.w = fmaxf(acc.w, 0.f);

    ((float4*)(g_x + (size_t)node * HH))[lane] = acc;

    __nv_bfloat162 h0 = make_bfloat162(__float2bfloat16(acc.x), __float2bfloat16(acc.y));
    __nv_bfloat162 h1 = make_bfloat162(__float2bfloat16(acc.z), __float2bfloat16(acc.w));
    __nv_bfloat162 l0 = make_bfloat162(
        __float2bfloat16(acc.x - __bfloat162float(h0.x)),
        __float2bfloat16(acc.y - __bfloat162float(h0.y)));
    __nv_bfloat162 l1 = make_bfloat162(
        __float2bfloat16(acc.z - __bfloat162float(h1.x)),
        __float2bfloat16(acc.w - __bfloat162float(h1.y)));
    ((__nv_bfloat162*)(g_xhi + (size_t)node * HH))[lane * 2] = h0;
    ((__nv_bfloat162*)(g_xhi + (size_t)node * HH))[lane * 2 + 1] = h1;
    ((__nv_bfloat162*)(g_xlo + (size_t)node * HH))[lane * 2] = l0;
    ((__nv_bfloat162*)(g_xlo + (size_t)node * HH))[lane * 2 + 1] = l1;
}

// ---------------- pool + action head + sos (fused, block per graph) --------
__global__ void k_pool_action_sos(const int* __restrict__ nodes_bs,
                                  const float* __restrict__ wA, const float* __restrict__ bA,
                                  const float* __restrict__ wAf, const float* __restrict__ bAf,
                                  const int* __restrict__ act, const float* __restrict__ embA,
                                  float* __restrict__ out) {
    int b = blockIdx.x, o = threadIdx.x;
    __shared__ float sg[HH], t1[HH];
    float s = 0.f;
    const float* xp = g_x + (size_t)b * (NN / BB) * HH + o;
#pragma unroll 4
    for (int j = 0; j < NN / BB; j++) s += xp[j * HH];
    s /= (float)nodes_bs[b];
    g_hG[b * HH + o] = s;
    sg[o] = s;
    g_seqin[(size_t)b * LL * HH + o] = embA[act[b] * HH + o];
    __syncthreads();
    float acc = bA[o];
    const float* w = wA + o * HH;
#pragma unroll 8
    for (int h = 0; h < HH; h += 4) {
        float4 w4 = *(const float4*)&w[h];
        acc += sg[h] * w4.x + sg[h + 1] * w4.y + sg[h + 2] * w4.z + sg[h + 3] * w4.w;
    }
    t1[o] = fmaxf(acc, 0.f);
    __syncthreads();
    if (o < VAC) {
        float a2 = bAf[o];
        const float* w2 = wAf + o * HH;
#pragma unroll 8
        for (int h = 0; h < HH; h += 4) {
            float4 w4 = *(const float4*)&w2[h];
            a2 += t1[h] * w4.x + t1[h + 1] * w4.y + t1[h + 2] * w4.z + t1[h + 3] * w4.w;
        }
        out[b * VAC + o] = a2;
    }
}

// ---------------- GRU input assembly ----------------
__global__ void k_seqemb(const float* __restrict__ seq) {
    int t = blockIdx.x;
    int b = blockIdx.y;
    int h = threadIdx.x;
    __shared__ float s[NN / BB];
    s[h] = seq[(size_t)(b * (NN / BB) + h) * LL + t];
    __syncthreads();
    float acc = 0.f;
    for (int j = 0; j < NN / BB; j++) {
        float sv = s[j];
        if (sv != 0.0f)
            acc += sv * g_x[(size_t)(b * (NN / BB) + j) * HH + h];
    }
    g_seqin[((size_t)b * LL + t + 1) * HH + h] = acc;
}

// ---------------- generic C[m,j] = dot(X[m,:], W[j, woff:woff+128]) + bias -
__global__ void k_gemmT(const float* __restrict__ X, const float* __restrict__ W,
                        int ldw, int woff, const float* __restrict__ bias,
                        float* __restrict__ out) {
    int m0 = blockIdx.x * 16;
    int j = threadIdx.x;
    int J = blockDim.x;
    __shared__ float Xs[16 * HH];
    for (int idx = j; idx < 16 * HH; idx += J) Xs[idx] = X[(size_t)m0 * HH + idx];
    __syncthreads();
    float acc[16];
    float bv = bias ? bias[j] : 0.f;
#pragma unroll
    for (int m = 0; m < 16; m++) acc[m] = bv;
    const float* wr = W + (size_t)j * ldw + woff;
    for (int h = 0; h < HH; h += 4) {
        float4 w4 = *(const float4*)&wr[h];
#pragma unroll
        for (int m = 0; m < 16; m++) {
            acc[m] += Xs[m * HH + h] * w4.x;
            acc[m] += Xs[m * HH + h + 1] * w4.y;
            acc[m] += Xs[m * HH + h + 2] * w4.z;
            acc[m] += Xs[m * HH + h + 3] * w4.w;
        }
    }
#pragma unroll
    for (int m = 0; m < 16; m++) out[(size_t)(m0 + m) * J + j] = acc[m];
}

// node-head A and C in one grid
__global__ void k_gemmT_AC(const float* __restrict__ W, const float* __restrict__ biasN) {
    int bx = blockIdx.x;
    const float* X;
    const float* bias;
    int woff;
    float* out;
    int m0;
    if (bx < (BB * LL) / 16) {
        X = g_seqout; woff = 0; bias = nullptr; out = g_A; m0 = bx * 16;
    } else {
        X = g_x; woff = HH; bias = biasN; out = g_C; m0 = (bx - (BB * LL) / 16) * 16;
    }
    int j = threadIdx.x;
    __shared__ float Xs[16 * HH];
    for (int idx = j; idx < 16 * HH; idx += HH) Xs[idx] = X[(size_t)m0 * HH + idx];
    __syncthreads();
    float acc[16];
    float bv = bias ? bias[j] : 0.f;
#pragma unroll
    for (int m = 0; m < 16; m++) acc[m] = bv;
    const float* wr = W + (size_t)j * (2 * HH) + woff;
    for (int h = 0; h < HH; h += 4) {
        float4 w4 = *(const float4*)&wr[h];
#pragma unroll
        for (int m = 0; m < 16; m++) {
            acc[m] += Xs[m * HH + h] * w4.x;
            acc[m] += Xs[m * HH + h + 1] * w4.y;
            acc[m] += Xs[m * HH + h + 2] * w4.z;
            acc[m] += Xs[m * HH + h + 3] * w4.w;
        }
    }
#pragma unroll
    for (int m = 0; m < 16; m++) out[(size_t)(m0 + m) * HH + j] = acc[m];
}

// ---------------- GRU scan (float4 smem reads, R7 version) ----------------
__global__ void __launch_bounds__(384) k_gru(const float* __restrict__ w_hh,
                                             const float* __restrict__ b_hh,
                                             const int* __restrict__ len_seq) {
    int b = blockIdx.x;
    int g = threadIdx.x;
    __shared__ __align__(16) float sh[HH];
    __shared__ float sg[3 * HH];
    if (g < HH) sh[g] = g_hG[b * HH + g];
    int ls = len_seq[b];
    const float* w = w_hh + (size_t)g * HH;
    float bg = b_hh[g];
    __syncthreads();
    const float4* sh4 = (const float4*)sh;
    for (int t = 0; t < LL; t++) {
        float acc = bg;
#pragma unroll
        for (int k = 0; k < HH / 4; k++) {
            float4 w4 = *(const float4*)&w[k * 4];
            float4 h4 = sh4[k];
            acc += h4.x * w4.x + h4.y * w4.y + h4.z * w4.z + h4.w * w4.w;
        }
        sg[g] = acc;
        __syncthreads();
        if (g < HH) {
            const float* xwp = g_xw + ((size_t)b * LL + t) * (3 * HH);
            float rg = 1.f / (1.f + expf(-(xwp[g] + sg[g])));
            float zg = 1.f / (1.f + expf(-(xwp[HH + g] + sg[HH + g])));
            float ng = tanhf(xwp[2 * HH + g] + rg * sg[2 * HH + g]);
            float hnew = (1.f - zg) * ng + zg * sh[g];
            g_seqout[((size_t)b * LL + t) * HH + g] = (t < ls) ? hnew : 0.f;
            sh[g] = hnew;
        }
        __syncthreads();
    }
}

// ---------------- node logits: 4-way ILP over t ----------------------------
__global__ void k_logits(const int* __restrict__ bs, const float* __restrict__ wf,
                         const float* __restrict__ bf, float* __restrict__ outN) {
    int i = (blockIdx.x * blockDim.x + threadIdx.x) >> 5;
    int lane = threadIdx.x & 31;
    if (i >= NN) return;
    int b = bs[i];
    float4 c4 = *(const float4*)&g_C[(size_t)i * HH + lane * 4];
    float4 w4 = *(const float4*)&wf[lane * 4];
    float bias = bf[0];
    const float* Ab = g_A + (size_t)b * LL * HH;
    for (int t0 = 0; t0 < LL; t0 += 4) {
        float s[4];
#pragma unroll
        for (int q = 0; q < 4; q++) {
            float4 a4 = *(const float4*)&Ab[(t0 + q) * HH + lane * 4];
            s[q] = fmaxf(a4.x + c4.x, 0.f) * w4.x
                 + fmaxf(a4.y + c4.y, 0.f) * w4.y
                 + fmaxf(a4.z + c4.z, 0.f) * w4.z
                 + fmaxf(a4.w + c4.w, 0.f) * w4.w;
        }
#pragma unroll
        for (int off = 16; off; off >>= 1) {
#pragma unroll
            for (int q = 0; q < 4; q++)
                s[q] += __shfl_down_sync(0xffffffffu, s[q], off);
        }
        if (lane == 0) {
#pragma unroll
            for (int q = 0; q < 4; q++)
                outN[(size_t)i * LL + t0 + q] = s[q] + bias;
        }
    }
}

// ---------------- per-graph softmax, coalesced -----------------------------
#define NPG (NN / BB)
__global__ void __launch_bounds__(256) k_softmax2(float* __restrict__ outN) {
    int b = blockIdx.x;
    __shared__ float sm[LL * 129];
    __shared__ float smax[LL], ssum[LL];
    int tid = threadIdx.x;
    float* base = outN + (size_t)b * NPG * LL;

    for (int idx = tid; idx < NPG * LL; idx += 256) {
        int node = idx / LL, t = idx % LL;
        sm[t * 129 + node] = base[idx];
    }
    __syncthreads();

    int w = tid >> 5, lane = tid & 31;
    for (int t = w; t < LL; t += 8) {
        float v0 = sm[t * 129 + lane];
        float v1 = sm[t * 129 + lane + 32];
        float v2 = sm[t * 129 + lane + 64];
        float v3 = sm[t * 129 + lane + 96];
        float mx = fmaxf(fmaxf(v0, v1), fmaxf(v2, v3));
#pragma unroll
        for (int off = 16; off; off >>= 1)
            mx = fmaxf(mx, __shfl_xor_sync(0xffffffffu, mx, off));
        float e = expf(v0 - mx) + expf(v1 - mx) + expf(v2 - mx) + expf(v3 - mx);
#pragma unroll
        for (int off = 16; off; off >>= 1) e += __shfl_xor_sync(0xffffffffu, e, off);
        if (lane == 0) { smax[t] = mx; ssum[t] = e; }
    }
    __syncthreads();

    for (int idx = tid; idx < NPG * LL; idx += 256) {
        int node = idx / LL, t = idx % LL;
        base[idx] = expf(sm[t * 129 + node] - smax[t]) / ssum[t];
    }
}

// ---------------- launch ----------------
extern "C" void kernel_launch(void* const* d_in, const int* in_sizes, int n_in,
                              void* d_out, int out_size) {
    const int* nodeTypes   = (const int*)d_in[0];
    const int* edge_index  = (const int*)d_in[1];
    const int* edge_attr   = (const int*)d_in[2];
    const int* bs          = (const int*)d_in[3];
    const int* nodes_bs    = (const int*)d_in[4];
    const int* len_seq     = (const int*)d_in[5];
    const float* seq       = (const float*)d_in[6];
    const int* action_in   = (const int*)d_in[7];
    const float* emb_nodes = (const float*)d_in[8];
    const float* emb_act   = (const float*)d_in[9];
    const float* rgcn_rel  = (const float*)d_in[10];
    const float* rgcn_root = (const float*)d_in[11];
    const float* rgcn_bias = (const float*)d_in[12];
    const float* gru_w_ih  = (const float*)d_in[13];
    const float* gru_w_hh  = (const float*)d_in[14];
    const float* gru_b_ih  = (const float*)d_in[15];
    const float* gru_b_hh  = (const float*)d_in[16];
    const float* linA_w    = (const float*)d_in[17];
    const float* linA_b    = (const float*)d_in[18];
    const float* linAf_w   = (const float*)d_in[19];
    const float* linAf_b   = (const float*)d_in[20];
    const float* linN_w    = (const float*)d_in[21];
    const float* linN_b    = (const float*)d_in[22];
    const float* linNf_w   = (const float*)d_in[23];
    const float* linNf_b   = (const float*)d_in[24];

    float* out_action = (float*)d_out;
    float* out_nodes  = out_action + BB * VAC;

    float *p_seqin, *p_xw;
    cudaGetSymbolAddress((void**)&p_seqin, g_seqin);
    cudaGetSymbolAddress((void**)&p_xw, g_xw);

    cudaFuncSetAttribute(k_rgcn_mma, cudaFuncAttributeMaxDynamicSharedMemorySize, RGCN_SMEM);

    k_embed_split<<<(NN * HH) / 256, 256>>>(nodeTypes, emb_nodes);
    k_count<<<EE / 256, 256>>>(edge_index, edge_attr);
    k_convw<<<dim3(16, 27), 256>>>(rgcn_rel, rgcn_root);

    // 4: profiled slot — the tensor-core GEMM
    k_rgcn_mma<<<dim3(9, 64), 512, RGCN_SMEM>>>(rgcn_bias, 0);

    k_scan1<<<64, 1024>>>();
    k_scan2<<<1, 64>>>();
    k_scatter<<<EE / 256, 256>>>(edge_index, edge_attr);

    k_gather_relu<<<NN / 8, 256>>>();
    for (int li = 1; li < 3; li++) {
        k_rgcn_mma<<<dim3(9, 64), 512, RGCN_SMEM>>>(rgcn_bias, li);
        k_gather_relu<<<NN / 8, 256>>>();
    }

    k_pool_action_sos<<<BB, HH>>>(nodes_bs, linA_w, linA_b, linAf_w, linAf_b,
                                  action_in, emb_act, out_action);
    k_seqemb<<<dim3(LL - 1, BB), NN / BB>>>(seq);

    k_gemmT<<<(BB * LL) / 16, 3 * HH>>>(p_seqin, gru_w_ih, HH, 0, gru_b_ih, p_xw);
    k_gru<<<BB, 3 * HH>>>(gru_w_hh, gru_b_hh, len_seq);

    k_gemmT_AC<<<(BB * LL) / 16 + NN / 16, HH>>>(linN_w, linN_b);
    k_logits<<<NN / 8, 256>>>(bs, linNf_w, linNf_b, out_nodes);
    k_softmax2<<<BB, 256>>>(out_nodes);
}